// round 7
// baseline (speedup 1.0000x reference)
#include <cuda_runtime.h>
#include <cstdint>
#include <math.h>

#define B_    64
#define C_    256
#define T_    1024
#define H_    512
#define S_TOT 192
#define S_RX0 64
#define BETA  0.9f
#define THR   0.75f

// ---- output layout (flattened tuple, float32) ----
#define OUT_D  0
#define OUT_A  (B_*H_)
#define OUT_E  (2*B_*H_)
#define OUT_RX (3*B_*H_)
#define OUT_PX (3*B_*H_ + B_*2*C_*T_)

// ---- static device scratch ----
__device__ float        g_acc   [(size_t)S_TOT * T_ * C_];  // mixed (pre-bias) [s][t][c]
__device__ unsigned int g_trace [128 * C_ * 32];            // rx spike bits [rb][c][t/32]
__device__ int          g_spkcnt[S_TOT * C_];
__device__ float        g_feat  [3 * B_ * C_];
// W digit planes in imma B-fragment order: [img 2][digit 4][q 8][j 32][lane 32][reg 2]
__device__ uint32_t     g_Bfrag [2 * 4 * 16384];

// ======================= helpers =========================
__device__ __forceinline__ uint32_t smem_to_u32(const void* p) {
    uint32_t a;
    asm("{ .reg .u64 t; cvta.to.shared.u64 t, %1; cvt.u32.u64 %0, t; }" : "=r"(a) : "l"(p));
    return a;
}

#define LDMATRIX_X4(r0, r1, r2, r3, addr) \
    asm volatile("ldmatrix.sync.aligned.m8n8.x4.shared.b16 {%0,%1,%2,%3}, [%4];" \
        : "=r"(r0), "=r"(r1), "=r"(r2), "=r"(r3) : "r"(addr))

// D = A(s8) * B(s8) + C, s32 accumulate, m16n8k32
#define IMMA(d, a, b0, b1, c) \
    asm volatile("mma.sync.aligned.m16n8k32.row.col.s32.s8.s8.s32 " \
        "{%0,%1,%2,%3}, {%4,%5,%6,%7}, {%8,%9}, {%10,%11,%12,%13};" \
        : "=r"((d)[0]), "=r"((d)[1]), "=r"((d)[2]), "=r"((d)[3]) \
        : "r"((a)[0]), "r"((a)[1]), "r"((a)[2]), "r"((a)[3]), \
          "r"(b0), "r"(b1), \
          "r"((c)[0]), "r"((c)[1]), "r"((c)[2]), "r"((c)[3]))

// ============================================================================
// K0w: quantize W to q=rint(w*2^30), split into 4 balanced signed bytes
// (exact: q = d0*2^24 + d1*2^16 + d2*2^8 + d3), packed in imma B-fragment
// order. v decode: reg=v&1, lane=(v>>1)&31, j=(v>>6)&31, q=v>>11;
// n = j*8 + (lane>>2); k = q*32 + reg*16 + (lane&3)*4 + byte.
// grid dim3(2, 64) x 256 threads.
// ============================================================================
__global__ void k0w(const float* __restrict__ W_tx, const float* __restrict__ W_rx)
{
    const int img = blockIdx.x;                 // 0=tx, 1=rx
    const float* W = img ? W_rx : W_tx;
    const int v = blockIdx.y * 256 + threadIdx.x;   // 0..16383

    const int reg = v & 1, lane = (v >> 1) & 31, j = (v >> 6) & 31, q = v >> 11;
    const int n  = j * 8 + (lane >> 2);
    const int k0 = q * 32 + reg * 16 + (lane & 3) * 4;

    uint32_t out[4] = {0u, 0u, 0u, 0u};
    #pragma unroll
    for (int e = 0; e < 4; e++) {
        const float w = W[n * 256 + k0 + e];
        int qw = __float2int_rn(w * 1073741824.0f);   // w * 2^30 (exact scale)
        const int d3 = (int)(signed char)(qw & 0xff); qw = (qw - d3) >> 8;
        const int d2 = (int)(signed char)(qw & 0xff); qw = (qw - d2) >> 8;
        const int d1 = (int)(signed char)(qw & 0xff); qw = (qw - d1) >> 8;
        const int d0 = qw;                             // |d0| <= ~68, fits s8
        out[0] |= ((uint32_t)(d0 & 0xff)) << (8 * e);
        out[1] |= ((uint32_t)(d1 & 0xff)) << (8 * e);
        out[2] |= ((uint32_t)(d2 & 0xff)) << (8 * e);
        out[3] |= ((uint32_t)(d3 & 0xff)) << (8 * e);
    }
    #pragma unroll
    for (int d = 0; d < 4; d++)
        g_Bfrag[(img * 4 + d) * 16384 + v] = out[d];
}

// ============================================================================
// K_GEMM v2: g_acc[s][t0..+127][nb*64..+63] = spikes @ W^T, exact 4-digit imma
// with 4 INDEPENDENT s32 digit accumulators (no inter-IMMA ALU; fold once in
// epilogue — bit-identical to pair-folded version, 2x the IMMA ILP).
// grid 6144 CTAs (s x 8 tblocks x 4 n-blocks), 512 threads = 16 warps
// (4 wm x 4 wn), warp tile 32t x 16n, 4 digit accs per m16n8 tile.
// smem: A 128x272B + 4 B digit planes x 16KB = 100352 B.
// ============================================================================
#define SM_A_BYTES 34816            // 128 * 272
#define SM_TOTAL   (SM_A_BYTES + 65536)

__global__ void __launch_bounds__(512, 1) k_gemm(const float* __restrict__ tx,
                                                 const float* __restrict__ rxsp)
{
    extern __shared__ unsigned char sm[];
    const uint32_t a_base = smem_to_u32(sm);

    const int tid = threadIdx.x, wid = tid >> 5, lane = tid & 31;
    const int wm = wid >> 2, wn = wid & 3;

    const int bx = blockIdx.x;
    const int s  = bx >> 5;
    const int tb = (bx >> 2) & 7;
    const int nb = bx & 3;
    const int t0 = tb * 128;

    const float* src = (s < S_RX0) ? tx + (size_t)s * C_ * T_
                                   : rxsp + (size_t)(s - S_RX0) * C_ * T_;
    const uint32_t* Bimg = g_Bfrag + ((s < S_RX0) ? 0 : 4 * 16384);

    // ---- phase 1: gmem -> byte staging [c 256][tq 32] u32 (4 t's per u32),
    // stride 33 u32 per channel row. Staging lives in the B region.
    uint32_t* stg = (uint32_t*)(sm + SM_A_BYTES);
    #pragma unroll
    for (int i = 0; i < 16; i++) {
        const int task = tid + i * 512;           // 0..8191
        const int c = task >> 5, tq = task & 31;
        const float4 f = *(const float4*)(src + (size_t)c * T_ + t0 + tq * 4);
        const uint32_t p = (f.x > 0.5f ? 0x1u : 0u) | (f.y > 0.5f ? 0x100u : 0u)
                         | (f.z > 0.5f ? 0x10000u : 0u) | (f.w > 0.5f ? 0x1000000u : 0u);
        stg[c * 33 + tq] = p;
    }
    __syncthreads();

    // ---- phase 2: staging -> A tile int8 [t 128][k=c 256], row stride 272B.
    #pragma unroll
    for (int i = 0; i < 4; i++) {
        const int task = tid + i * 512;           // 0..2047
        const int t = task & 127, u = task >> 7;  // u = 16-byte unit 0..15
        const int tq = t >> 2, sel = (t & 3) * 8;
        uint32_t o[4];
        #pragma unroll
        for (int k4 = 0; k4 < 4; k4++) {
            const uint32_t b0 = stg[(u * 16 + k4 * 4 + 0) * 33 + tq] >> sel;
            const uint32_t b1 = stg[(u * 16 + k4 * 4 + 1) * 33 + tq] >> sel;
            const uint32_t b2 = stg[(u * 16 + k4 * 4 + 2) * 33 + tq] >> sel;
            const uint32_t b3 = stg[(u * 16 + k4 * 4 + 3) * 33 + tq] >> sel;
            o[k4] = (b0 & 0xffu) | ((b1 & 0xffu) << 8) | ((b2 & 0xffu) << 16) | ((b3 & 0xffu) << 24);
        }
        *(uint4*)(sm + t * 272 + u * 16) = make_uint4(o[0], o[1], o[2], o[3]);
    }
    __syncthreads();

    // ---- copy 4 digit B planes (this CTA's 64-col n-block) into smem
    // dst u4 index i: d=i>>10, q=(i>>7)&7, jl=(i>>4)&7, r=i&15
    {
        const uint4* src4 = (const uint4*)Bimg;
        uint4* dst4 = (uint4*)(sm + SM_A_BYTES);
        #pragma unroll
        for (int i = tid; i < 4096; i += 512) {
            const int d = i >> 10, q = (i >> 7) & 7, jl = (i >> 4) & 7, r = i & 15;
            dst4[i] = src4[d * 4096 + q * 512 + (nb * 8 + jl) * 16 + r];
        }
    }
    __syncthreads();

    const uint32_t* smB = (const uint32_t*)(sm + SM_A_BYTES);

    int acc[2][2][4][4];
    #pragma unroll
    for (int mt = 0; mt < 2; mt++)
        #pragma unroll
        for (int nt = 0; nt < 2; nt++)
            #pragma unroll
            for (int d = 0; d < 4; d++)
                #pragma unroll
                for (int e = 0; e < 4; e++) acc[mt][nt][d][e] = 0;

    const int arow = wm * 32 + (lane & 15);

    #pragma unroll 1
    for (int q = 0; q < 8; q++) {
        uint32_t af[2][4];
        const int chunk = 2 * q + (lane >> 4);
        #pragma unroll
        for (int mt = 0; mt < 2; mt++) {
            const uint32_t addr = a_base + (arow + mt * 16) * 272 + (chunk << 4);
            LDMATRIX_X4(af[mt][0], af[mt][1], af[mt][2], af[mt][3], addr);
        }
        uint2 bf[2][4];
        #pragma unroll
        for (int nt = 0; nt < 2; nt++)
            #pragma unroll
            for (int d = 0; d < 4; d++)
                bf[nt][d] = *(const uint2*)(smB + d * 4096 + q * 512 + (wn * 2 + nt) * 64 + lane * 2);
        #pragma unroll
        for (int mt = 0; mt < 2; mt++)
            #pragma unroll
            for (int nt = 0; nt < 2; nt++)
                #pragma unroll
                for (int d = 0; d < 4; d++)
                    IMMA(acc[mt][nt][d], af[mt], bf[nt][d].x, bf[nt][d].y, acc[mt][nt][d]);
    }

    // ---- epilogue: fold digits once; single RNE rounding per output.
    // hi = (sum_d0<<8)+sum_d1 (weight 2^16), lo = (sum_d2<<8)+sum_d3 (weight 1)
    // val = hi*2^-14 + lo*2^-30; |hi|,|lo| < 2^24 so float converts are exact.
    const int g = lane >> 2;
    #pragma unroll
    for (int mt = 0; mt < 2; mt++) {
        const int row = t0 + wm * 32 + mt * 16 + g;
        float* prow = g_acc + ((size_t)s * T_ + row) * C_;
        #pragma unroll
        for (int nt = 0; nt < 2; nt++) {
            const int col = nb * 64 + wn * 16 + nt * 8 + (lane & 3) * 2;
            float v[4];
            #pragma unroll
            for (int e = 0; e < 4; e++) {
                const int hi = (acc[mt][nt][0][e] << 8) + acc[mt][nt][1][e];
                const int lo = (acc[mt][nt][2][e] << 8) + acc[mt][nt][3][e];
                v[e] = fmaf((float)lo, 0x1p-30f, (float)hi * 0x1p-14f);
            }
            *(float2*)(prow + col)          = make_float2(v[0], v[1]);
            *(float2*)(prow + 8 * C_ + col) = make_float2(v[2], v[3]);
        }
    }
}

// ============================================================================
// K2b: LIF recurrence only. Thread per (s,c), 1024 steps, loads batched x32.
// ============================================================================
__global__ void k2b_scan(const float* __restrict__ b_tx, const float* __restrict__ b_rx)
{
    const int gid = blockIdx.x * 128 + threadIdx.x;   // 0..49151
    const int s = gid >> 8, c = gid & 255;
    const bool is_rx = (s >= S_RX0);
    const float bias = is_rx ? b_rx[c] : b_tx[c];
    const float* ap = g_acc + (size_t)s * T_ * C_ + c;
    const unsigned tb = is_rx ? ((unsigned)(s - S_RX0) * C_ + c) * 32u : 0u;

    float m = 0.0f, sub = 0.0f;
    int cnt = 0;

    #pragma unroll 1
    for (int t32 = 0; t32 < 32; ++t32) {
        float av[32];
        #pragma unroll
        for (int k = 0; k < 32; ++k)
            av[k] = ap[(size_t)(t32 * 32 + k) * C_];
        unsigned word = 0;
        #pragma unroll
        for (int k = 0; k < 32; ++k) {
            m = BETA * m + (av[k] + bias) - sub;
            const bool sp = m > THR;
            sub = sp ? THR : 0.0f;
            word |= (sp ? 1u : 0u) << k;
        }
        if (is_rx) g_trace[tb + t32] = word;
        cnt += __popc(word);
    }
    g_spkcnt[s * C_ + c] = cnt;
}

// ============================================================================
// K3: expand rx spike bits -> float32 trace in d_out (coalesced LUT expansion)
// ============================================================================
__global__ void k3_expand(float* __restrict__ out)
{
    __shared__ float4 lut[16];
    if (threadIdx.x < 16)
        lut[threadIdx.x] = make_float4((float)(threadIdx.x & 1), (float)((threadIdx.x >> 1) & 1),
                                       (float)((threadIdx.x >> 2) & 1), (float)((threadIdx.x >> 3) & 1));
    __syncthreads();

    const int row = blockIdx.x * 8 + (threadIdx.x >> 5);   // 0..32767
    const int l   = threadIdx.x & 31;
    const unsigned word = g_trace[(size_t)row * 32 + l];
    float4* dst = (float4*)(out + OUT_RX + (size_t)row * T_);
    #pragma unroll
    for (int k = 0; k < 8; k++) {
        const int t4   = k * 32 + l;
        const unsigned wsrc = __shfl_sync(0xffffffffu, word, t4 >> 3);
        const unsigned nib  = (wsrc >> ((t4 & 7) * 4)) & 0xFu;
        dst[t4] = lut[nib];
    }
}

// ============================================================================
// K4a: features + layernorm + spike_proxy
// ============================================================================
__device__ __forceinline__ float blk_sum(float v, float* red, int c)
{
    red[c] = v; __syncthreads();
    #pragma unroll
    for (int off = 128; off > 0; off >>= 1) {
        if (c < off) red[c] += red[c + off];
        __syncthreads();
    }
    float s = red[0]; __syncthreads();
    return s;
}

__global__ void k4a_feat(float* __restrict__ out)
{
    __shared__ float red[256];
    const int b = blockIdx.x, c = threadIdx.x;
    const int cd = g_spkcnt[b * C_ + c];
    const int cl = g_spkcnt[(S_RX0 + b * 2 + 0) * C_ + c];
    const int cr = g_spkcnt[(S_RX0 + b * 2 + 1) * C_ + c];

    out[OUT_PX + (size_t)(b * 2 + 0) * C_ + c] = (float)cl;
    out[OUT_PX + (size_t)(b * 2 + 1) * C_ + c] = (float)cr;

    float f[3];
    f[0] = (float)cd        * (1.0f / 1024.0f);
    f[1] = (float)(cl - cr) * (1.0f / 1024.0f);
    f[2] = (float)(cl + cr) * (1.0f / 1024.0f);

    #pragma unroll
    for (int typ = 0; typ < 3; typ++) {
        const float mu = blk_sum(f[typ], red, c) * (1.0f / 256.0f);
        const float xc = f[typ] - mu;
        const float var = blk_sum(xc * xc, red, c) * (1.0f / 256.0f);
        g_feat[(typ * B_ + b) * C_ + c] = xc / sqrtf(var + 1e-5f);
    }
}

// ============================================================================
// K4b: heads — [64x256]@[256x512]^T + bias, gain, residual, relu.
// ============================================================================
__global__ void k4b_head(const float* __restrict__ Wd, const float* __restrict__ bd,
                         const float* __restrict__ Wa, const float* __restrict__ ba,
                         const float* __restrict__ We, const float* __restrict__ be,
                         const float* __restrict__ base_d, const float* __restrict__ base_a,
                         const float* __restrict__ base_e,
                         const float* __restrict__ gd, const float* __restrict__ ga,
                         const float* __restrict__ ge,
                         float* __restrict__ out)
{
    extern __shared__ float x_sh[];   // 64*256 floats
    const int typ = blockIdx.x >> 6;
    const int h0  = (blockIdx.x & 63) * 8;

    const float* feat = g_feat + (size_t)typ * B_ * C_;
    for (int i = threadIdx.x; i < B_ * C_; i += 256) x_sh[i] = feat[i];
    __syncthreads();

    const float* Wm   = (typ == 0) ? Wd : (typ == 1) ? Wa : We;
    const float* bm   = (typ == 0) ? bd : (typ == 1) ? ba : be;
    const float* bsp  = (typ == 0) ? base_d : (typ == 1) ? base_a : base_e;
    const float  g    = (typ == 0) ? *gd : (typ == 1) ? *ga : *ge;
    const float  sg   = 0.3f / (1.0f + expf(-g));
    const size_t ooff = (typ == 0) ? OUT_D : (typ == 1) ? OUT_A : OUT_E;

    const int lane = threadIdx.x & 31;
    const int h    = h0 + (threadIdx.x >> 5);

    const float4* wrow = (const float4*)(Wm + (size_t)h * C_);
    const float4 w0 = wrow[lane * 2];
    const float4 w1 = wrow[lane * 2 + 1];
    const float  bh = bm[h];

    for (int b = 0; b < B_; b++) {
        const float4* xb = (const float4*)(x_sh + b * C_ + lane * 8);
        const float4 x0 = xb[0], x1 = xb[1];
        float p = w0.x * x0.x + w0.y * x0.y + w0.z * x0.z + w0.w * x0.w
                + w1.x * x1.x + w1.y * x1.y + w1.z * x1.z + w1.w * x1.w;
        #pragma unroll
        for (int off = 16; off > 0; off >>= 1)
            p += __shfl_xor_sync(0xffffffffu, p, off);
        if (lane == 0) {
            const float r = p + bh;
            const float v = bsp[(size_t)b * H_ + h] + sg * r;
            out[ooff + (size_t)b * H_ + h] = v > 0.0f ? v : 0.0f;
        }
    }
}

// ============================================================================
extern "C" void kernel_launch(void* const* d_in, const int* in_sizes, int n_in,
                              void* d_out, int out_size)
{
    const float* tx    = (const float*)d_in[0];
    const float* rxsp  = (const float*)d_in[1];
    const float* bsd   = (const float*)d_in[2];
    const float* bsa   = (const float*)d_in[3];
    const float* bse   = (const float*)d_in[4];
    const float* W_tx  = (const float*)d_in[5];
    const float* b_tx  = (const float*)d_in[6];
    const float* W_rx  = (const float*)d_in[7];
    const float* b_rx  = (const float*)d_in[8];
    const float* Wd    = (const float*)d_in[9];
    const float* bd    = (const float*)d_in[10];
    const float* Wa    = (const float*)d_in[11];
    const float* ba    = (const float*)d_in[12];
    const float* We    = (const float*)d_in[13];
    const float* be    = (const float*)d_in[14];
    const float* gd    = (const float*)d_in[15];
    const float* ga    = (const float*)d_in[16];
    const float* ge    = (const float*)d_in[17];
    float* out = (float*)d_out;

    static bool attr_set = false;
    if (!attr_set) {
        cudaFuncSetAttribute(k_gemm, cudaFuncAttributeMaxDynamicSharedMemorySize, SM_TOTAL);
        cudaFuncSetAttribute(k4b_head, cudaFuncAttributeMaxDynamicSharedMemorySize, 65536);
        attr_set = true;
    }

    k0w<<<dim3(2, 64), 256>>>(W_tx, W_rx);
    k_gemm<<<S_TOT * 32, 512, SM_TOTAL>>>(tx, rxsp);
    k2b_scan<<<384, 128>>>(b_tx, b_rx);
    k3_expand<<<4096, 256>>>(out);
    k4a_feat<<<B_, 256>>>(out);
    k4b_head<<<3 * 64, 256, 65536>>>(Wd, bd, Wa, ba, We, be, bsd, bsa, bse, gd, ga, ge, out);
}

// round 8
// speedup vs baseline: 1.1336x; 1.1336x over previous
#include <cuda_runtime.h>
#include <cstdint>
#include <math.h>

#define B_    64
#define C_    256
#define T_    1024
#define H_    512
#define S_TOT 192
#define S_RX0 64
#define S_MMA 78        // seqs [0,78) -> IMMA engine; [78,192) -> scalar engine
#define BETA  0.9f
#define THR   0.75f
#define LCAP  120
#define TT    128
#define OB    64

// ---- output layout (flattened tuple, float32) ----
#define OUT_D  0
#define OUT_A  (B_*H_)
#define OUT_E  (2*B_*H_)
#define OUT_RX (3*B_*H_)
#define OUT_PX (3*B_*H_ + B_*2*C_*T_)

// ---- static device scratch ----
__device__ float        g_acc   [(size_t)S_TOT * T_ * C_];  // mixed (pre-bias) [s][t][c]
__device__ unsigned int g_trace [128 * C_ * 32];            // rx spike bits [rb][c][t/32]
__device__ int          g_spkcnt[S_TOT * C_];
__device__ float        g_feat  [3 * B_ * C_];
__device__ uint4        g_idx_w [S_TOT * T_ * (LCAP/8)];    // scalar engine index lists
__device__ unsigned short g_cnt [S_TOT * T_];
// W digit planes in imma B-fragment order: [img 2][digit 4][q 8][j 32][lane 32][reg 2]
__device__ uint32_t     g_Bfrag [2 * 4 * 16384];

// ======================= helpers =========================
__device__ __forceinline__ uint32_t smem_to_u32(const void* p) {
    uint32_t a;
    asm("{ .reg .u64 t; cvta.to.shared.u64 t, %1; cvt.u32.u64 %0, t; }" : "=r"(a) : "l"(p));
    return a;
}

#define LDMATRIX_X4(r0, r1, r2, r3, addr) \
    asm volatile("ldmatrix.sync.aligned.m8n8.x4.shared.b16 {%0,%1,%2,%3}, [%4];" \
        : "=r"(r0), "=r"(r1), "=r"(r2), "=r"(r3) : "r"(addr))

#define IMMA(d, a, b0, b1, c) \
    asm volatile("mma.sync.aligned.m16n8k32.row.col.s32.s8.s8.s32 " \
        "{%0,%1,%2,%3}, {%4,%5,%6,%7}, {%8,%9}, {%10,%11,%12,%13};" \
        : "=r"((d)[0]), "=r"((d)[1]), "=r"((d)[2]), "=r"((d)[3]) \
        : "r"((a)[0]), "r"((a)[1]), "r"((a)[2]), "r"((a)[3]), \
          "r"(b0), "r"(b1), \
          "r"((c)[0]), "r"((c)[1]), "r"((c)[2]), "r"((c)[3]))

// ============================================================================
// K0w: quantize W to q=rint(w*2^30), 4 balanced signed byte digits (exact),
// packed in imma B-fragment order. grid dim3(2, 64) x 256 threads.
// ============================================================================
__global__ void k0w(const float* __restrict__ W_tx, const float* __restrict__ W_rx)
{
    const int img = blockIdx.x;
    const float* W = img ? W_rx : W_tx;
    const int v = blockIdx.y * 256 + threadIdx.x;

    const int reg = v & 1, lane = (v >> 1) & 31, j = (v >> 6) & 31, q = v >> 11;
    const int n  = j * 8 + (lane >> 2);
    const int k0 = q * 32 + reg * 16 + (lane & 3) * 4;

    uint32_t out[4] = {0u, 0u, 0u, 0u};
    #pragma unroll
    for (int e = 0; e < 4; e++) {
        const float w = W[n * 256 + k0 + e];
        int qw = __float2int_rn(w * 1073741824.0f);
        const int d3 = (int)(signed char)(qw & 0xff); qw = (qw - d3) >> 8;
        const int d2 = (int)(signed char)(qw & 0xff); qw = (qw - d2) >> 8;
        const int d1 = (int)(signed char)(qw & 0xff); qw = (qw - d1) >> 8;
        const int d0 = qw;
        out[0] |= ((uint32_t)(d0 & 0xff)) << (8 * e);
        out[1] |= ((uint32_t)(d1 & 0xff)) << (8 * e);
        out[2] |= ((uint32_t)(d2 & 0xff)) << (8 * e);
        out[3] |= ((uint32_t)(d3 & 0xff)) << (8 * e);
    }
    #pragma unroll
    for (int d = 0; d < 4; d++)
        g_Bfrag[(img * 4 + d) * 16384 + v] = out[d];
}

// ============================================================================
// K_MMA: exact 4-digit imma GEMM for s in [0, S_MMA).
// grid S_MMA*64 (s x 8 tb x 8 nb), 256 threads = 8 warps (4 wm x 2 wn),
// warp tile 32t x 16n. smem: A 128x272B + staging/B area 33.8KB = 68608 B.
// ============================================================================
#define SM_A_BYTES 34816            // 128 * 272
#define SM_MMA_TOTAL (SM_A_BYTES + 33792)

__global__ void __launch_bounds__(256, 1) k_mma(const float* __restrict__ tx,
                                                const float* __restrict__ rxsp)
{
    extern __shared__ unsigned char sm[];
    const uint32_t a_base = smem_to_u32(sm);

    const int tid = threadIdx.x, wid = tid >> 5, lane = tid & 31;
    const int wm = wid >> 1, wn = wid & 1;

    const int bx = blockIdx.x;
    const int s  = bx >> 6;
    const int tb = (bx >> 3) & 7;
    const int nb = bx & 7;
    const int t0 = tb * 128;

    const float* src = (s < S_RX0) ? tx + (size_t)s * C_ * T_
                                   : rxsp + (size_t)(s - S_RX0) * C_ * T_;
    const uint4* Bimg4 = (const uint4*)(g_Bfrag + ((s < S_RX0) ? 0 : 4 * 16384));

    // ---- phase 1: gmem -> byte staging [c 256][tq 32] u32, stride 33
    uint32_t* stg = (uint32_t*)(sm + SM_A_BYTES);
    #pragma unroll
    for (int i = 0; i < 32; i++) {
        const int task = tid + i * 256;           // 0..8191
        const int c = task >> 5, tq = task & 31;
        const float4 f = *(const float4*)(src + (size_t)c * T_ + t0 + tq * 4);
        const uint32_t p = (f.x > 0.5f ? 0x1u : 0u) | (f.y > 0.5f ? 0x100u : 0u)
                         | (f.z > 0.5f ? 0x10000u : 0u) | (f.w > 0.5f ? 0x1000000u : 0u);
        stg[c * 33 + tq] = p;
    }
    __syncthreads();

    // ---- phase 2: staging -> A tile int8 [t 128][k=c 256], row stride 272B
    #pragma unroll
    for (int i = 0; i < 8; i++) {
        const int task = tid + i * 256;           // 0..2047
        const int t = task & 127, u = task >> 7;
        const int tq = t >> 2, sel = (t & 3) * 8;
        uint32_t o[4];
        #pragma unroll
        for (int k4 = 0; k4 < 4; k4++) {
            const uint32_t b0 = stg[(u * 16 + k4 * 4 + 0) * 33 + tq] >> sel;
            const uint32_t b1 = stg[(u * 16 + k4 * 4 + 1) * 33 + tq] >> sel;
            const uint32_t b2 = stg[(u * 16 + k4 * 4 + 2) * 33 + tq] >> sel;
            const uint32_t b3 = stg[(u * 16 + k4 * 4 + 3) * 33 + tq] >> sel;
            o[k4] = (b0 & 0xffu) | ((b1 & 0xffu) << 8) | ((b2 & 0xffu) << 16) | ((b3 & 0xffu) << 24);
        }
        *(uint4*)(sm + t * 272 + u * 16) = make_uint4(o[0], o[1], o[2], o[3]);
    }
    __syncthreads();

    // ---- copy 4 digit B planes (this CTA's 32-col n-block): 2048 uint4
    {
        uint4* dst4 = (uint4*)(sm + SM_A_BYTES);
        #pragma unroll
        for (int i = tid; i < 2048; i += 256) {
            const int d = i >> 9, q = (i >> 6) & 7, jl = (i >> 4) & 3, r = i & 15;
            dst4[i] = Bimg4[d * 4096 + q * 512 + (nb * 4 + jl) * 16 + r];
        }
    }
    __syncthreads();

    const uint32_t* smB = (const uint32_t*)(sm + SM_A_BYTES);

    int acc[2][2][4][4];
    #pragma unroll
    for (int mt = 0; mt < 2; mt++)
        #pragma unroll
        for (int nt = 0; nt < 2; nt++)
            #pragma unroll
            for (int d = 0; d < 4; d++)
                #pragma unroll
                for (int e = 0; e < 4; e++) acc[mt][nt][d][e] = 0;

    const int arow = wm * 32 + (lane & 15);

    #pragma unroll 1
    for (int q = 0; q < 8; q++) {
        uint32_t af[2][4];
        const int chunk = 2 * q + (lane >> 4);
        #pragma unroll
        for (int mt = 0; mt < 2; mt++) {
            const uint32_t addr = a_base + (arow + mt * 16) * 272 + (chunk << 4);
            LDMATRIX_X4(af[mt][0], af[mt][1], af[mt][2], af[mt][3], addr);
        }
        uint2 bf[2][4];
        #pragma unroll
        for (int nt = 0; nt < 2; nt++)
            #pragma unroll
            for (int d = 0; d < 4; d++)
                bf[nt][d] = *(const uint2*)(smB + d * 2048 + q * 256 + (wn * 2 + nt) * 64 + lane * 2);
        #pragma unroll
        for (int mt = 0; mt < 2; mt++)
            #pragma unroll
            for (int nt = 0; nt < 2; nt++)
                #pragma unroll
                for (int d = 0; d < 4; d++)
                    IMMA(acc[mt][nt][d], af[mt], bf[nt][d].x, bf[nt][d].y, acc[mt][nt][d]);
    }

    // ---- epilogue: fold digits, single RNE rounding per output
    const int g = lane >> 2;
    #pragma unroll
    for (int mt = 0; mt < 2; mt++) {
        const int row = t0 + wm * 32 + mt * 16 + g;
        float* prow = g_acc + ((size_t)s * T_ + row) * C_;
        #pragma unroll
        for (int nt = 0; nt < 2; nt++) {
            const int col = nb * 32 + wn * 16 + nt * 8 + (lane & 3) * 2;
            float v[4];
            #pragma unroll
            for (int e = 0; e < 4; e++) {
                const int hi = (acc[mt][nt][0][e] << 8) + acc[mt][nt][1][e];
                const int lo = (acc[mt][nt][2][e] << 8) + acc[mt][nt][3][e];
                v[e] = fmaf((float)lo, 0x1p-30f, (float)hi * 0x1p-14f);
            }
            *(float2*)(prow + col)          = make_float2(v[0], v[1]);
            *(float2*)(prow + 8 * C_ + col) = make_float2(v[2], v[3]);
        }
    }
}

// ============================================================================
// K1: active-channel index lists for the SCALAR engine, s in [S_MMA, 192).
// Indices pre-multiplied by 33 (float2 stride of W_sh row).
// grid (192-S_MMA)*32 CTAs, 256 threads.
// ============================================================================
__global__ void k1_pack(const float* __restrict__ tx, const float* __restrict__ rxsp)
{
    __shared__ float tile[256 * 33];
    __shared__ __align__(16) unsigned short lists[32 * LCAP];
    __shared__ int cnts[32];

    const int s  = S_MMA + (blockIdx.x >> 5);
    const int t0 = (blockIdx.x & 31) * 32;
    const float* base = (s < S_RX0) ? (tx + (size_t)s * C_ * T_)
                                    : (rxsp + (size_t)(s - S_RX0) * C_ * T_);
    const int w = threadIdx.x >> 5, l = threadIdx.x & 31;

    #pragma unroll 4
    for (int i = 0; i < 32; i++) {
        int c = i * 8 + w;
        tile[c * 33 + l] = base[(size_t)c * T_ + t0 + l];
    }
    __syncthreads();

    for (int tt = w * 4; tt < w * 4 + 4; tt++) {
        int cnt = 0;
        #pragma unroll
        for (int g = 0; g < 8; g++) {
            float v = tile[(g * 32 + l) * 33 + tt];
            unsigned m = __ballot_sync(0xffffffffu, v > 0.5f);
            if (v > 0.5f) {
                int pos = cnt + __popc(m & ((1u << l) - 1u));
                if (pos < LCAP) lists[tt * LCAP + pos] = (unsigned short)((g * 32 + l) * 33);
            }
            cnt += __popc(m);
        }
        if (cnt > 112) cnt = 112;
        int padded = (cnt + 7) & ~7;
        if (l < padded - cnt) lists[tt * LCAP + cnt + l] = (unsigned short)(256 * 33);
        if (l == 0) cnts[tt] = padded;
    }
    __syncthreads();

    uint4* dst = g_idx_w + (size_t)(s * T_ + t0) * (LCAP/8);
    const uint4* srcw = (const uint4*)lists;
    for (int i = threadIdx.x; i < 32 * (LCAP/8); i += 256) dst[i] = srcw[i];
    if (threadIdx.x < 32)
        g_cnt[s * T_ + t0 + threadIdx.x] = (unsigned short)cnts[threadIdx.x];
}

// ============================================================================
// K2a: scalar sparse mix for s in [S_MMA, 192). grid dim3(8, 4, 114), 256 thr.
// ============================================================================
__global__ void k2a_mix(const float* __restrict__ W_tx, const float* __restrict__ W_rx)
{
    extern __shared__ unsigned char smem_raw[];
    float*          W_sh   = (float*)smem_raw;                        // 257*66*4 = 67848
    unsigned short* lists  = (unsigned short*)(smem_raw + 67856);     // 30720
    unsigned short* cnt_sh = (unsigned short*)(smem_raw + 98576);

    const int tid = threadIdx.x;
    const int s   = S_MMA + blockIdx.z;
    const int o0  = blockIdx.y * OB;
    const int t0  = blockIdx.x * TT;
    const float* W = (s < S_RX0) ? W_tx : W_rx;

    #pragma unroll 4
    for (int idx = tid; idx < OB * C_; idx += 256) {
        int r = idx >> 8, c = idx & 255;
        W_sh[c * 66 + r] = W[(size_t)(o0 + r) * C_ + c];
    }
    if (tid < 66) W_sh[256 * 66 + tid] = 0.0f;

    {
        const uint4* src = g_idx_w + (size_t)(s * T_ + t0) * (LCAP/8);
        uint4* dstl = (uint4*)lists;
        #pragma unroll 2
        for (int i = tid; i < TT * (LCAP/8); i += 256) dstl[i] = src[i];
        if (tid < TT) cnt_sh[tid] = g_cnt[s * T_ + t0 + tid];
    }
    __syncthreads();

    const int w = tid >> 5, lane = tid & 31;
    const float2* Wt2 = (const float2*)W_sh + lane;

    #pragma unroll 1
    for (int tslot = 0; tslot < TT / 8; ++tslot) {
        const int tt = w * (TT / 8) + tslot;
        const int n8 = cnt_sh[tt] >> 3;
        const uint4* lw = (const uint4*)(lists + tt * LCAP);
        float a0x = 0.f, a0y = 0.f, a1x = 0.f, a1y = 0.f;
        float a2x = 0.f, a2y = 0.f, a3x = 0.f, a3y = 0.f;
        #pragma unroll 1
        for (int j = 0; j < n8; ++j) {
            uint4 v = lw[j];
            float2 w0 = Wt2[v.x & 0xffffu];  a0x += w0.x; a0y += w0.y;
            float2 w1 = Wt2[v.x >> 16];      a1x += w1.x; a1y += w1.y;
            float2 w2 = Wt2[v.y & 0xffffu];  a2x += w2.x; a2y += w2.y;
            float2 w3 = Wt2[v.y >> 16];      a3x += w3.x; a3y += w3.y;
            float2 w4 = Wt2[v.z & 0xffffu];  a0x += w4.x; a0y += w4.y;
            float2 w5 = Wt2[v.z >> 16];      a1x += w5.x; a1y += w5.y;
            float2 w6 = Wt2[v.w & 0xffffu];  a2x += w6.x; a2y += w6.y;
            float2 w7 = Wt2[v.w >> 16];      a3x += w7.x; a3y += w7.y;
        }
        float2 r;
        r.x = (a0x + a1x) + (a2x + a3x);
        r.y = (a0y + a1y) + (a2y + a3y);
        *(float2*)(g_acc + (size_t)(s * T_ + t0 + tt) * C_ + o0 + 2 * lane) = r;
    }
}

// ============================================================================
// K2b: LIF recurrence for seqs [s0, s0+ns). grid ns*2 x 128.
// ============================================================================
__global__ void k2b_scan(const float* __restrict__ b_tx, const float* __restrict__ b_rx,
                         int s0)
{
    const int gid = blockIdx.x * 128 + threadIdx.x;
    const int s = s0 + (gid >> 8), c = gid & 255;
    const bool is_rx = (s >= S_RX0);
    const float bias = is_rx ? b_rx[c] : b_tx[c];
    const float* ap = g_acc + (size_t)s * T_ * C_ + c;
    const unsigned tb = is_rx ? ((unsigned)(s - S_RX0) * C_ + c) * 32u : 0u;

    float m = 0.0f, sub = 0.0f;
    int cnt = 0;

    #pragma unroll 1
    for (int t32 = 0; t32 < 32; ++t32) {
        float av[32];
        #pragma unroll
        for (int k = 0; k < 32; ++k)
            av[k] = ap[(size_t)(t32 * 32 + k) * C_];
        unsigned word = 0;
        #pragma unroll
        for (int k = 0; k < 32; ++k) {
            m = BETA * m + (av[k] + bias) - sub;
            const bool sp = m > THR;
            sub = sp ? THR : 0.0f;
            word |= (sp ? 1u : 0u) << k;
        }
        if (is_rx) g_trace[tb + t32] = word;
        cnt += __popc(word);
    }
    g_spkcnt[s * C_ + c] = cnt;
}

// ============================================================================
// K3: expand rx spike bits -> float32 trace in d_out
// ============================================================================
__global__ void k3_expand(float* __restrict__ out)
{
    __shared__ float4 lut[16];
    if (threadIdx.x < 16)
        lut[threadIdx.x] = make_float4((float)(threadIdx.x & 1), (float)((threadIdx.x >> 1) & 1),
                                       (float)((threadIdx.x >> 2) & 1), (float)((threadIdx.x >> 3) & 1));
    __syncthreads();

    const int row = blockIdx.x * 8 + (threadIdx.x >> 5);
    const int l   = threadIdx.x & 31;
    const unsigned word = g_trace[(size_t)row * 32 + l];
    float4* dst = (float4*)(out + OUT_RX + (size_t)row * T_);
    #pragma unroll
    for (int k = 0; k < 8; k++) {
        const int t4   = k * 32 + l;
        const unsigned wsrc = __shfl_sync(0xffffffffu, word, t4 >> 3);
        const unsigned nib  = (wsrc >> ((t4 & 7) * 4)) & 0xFu;
        dst[t4] = lut[nib];
    }
}

// ============================================================================
// K4a: features + layernorm + spike_proxy
// ============================================================================
__device__ __forceinline__ float blk_sum(float v, float* red, int c)
{
    red[c] = v; __syncthreads();
    #pragma unroll
    for (int off = 128; off > 0; off >>= 1) {
        if (c < off) red[c] += red[c + off];
        __syncthreads();
    }
    float s = red[0]; __syncthreads();
    return s;
}

__global__ void k4a_feat(float* __restrict__ out)
{
    __shared__ float red[256];
    const int b = blockIdx.x, c = threadIdx.x;
    const int cd = g_spkcnt[b * C_ + c];
    const int cl = g_spkcnt[(S_RX0 + b * 2 + 0) * C_ + c];
    const int cr = g_spkcnt[(S_RX0 + b * 2 + 1) * C_ + c];

    out[OUT_PX + (size_t)(b * 2 + 0) * C_ + c] = (float)cl;
    out[OUT_PX + (size_t)(b * 2 + 1) * C_ + c] = (float)cr;

    float f[3];
    f[0] = (float)cd        * (1.0f / 1024.0f);
    f[1] = (float)(cl - cr) * (1.0f / 1024.0f);
    f[2] = (float)(cl + cr) * (1.0f / 1024.0f);

    #pragma unroll
    for (int typ = 0; typ < 3; typ++) {
        const float mu = blk_sum(f[typ], red, c) * (1.0f / 256.0f);
        const float xc = f[typ] - mu;
        const float var = blk_sum(xc * xc, red, c) * (1.0f / 256.0f);
        g_feat[(typ * B_ + b) * C_ + c] = xc / sqrtf(var + 1e-5f);
    }
}

// ============================================================================
// K4b: heads
// ============================================================================
__global__ void k4b_head(const float* __restrict__ Wd, const float* __restrict__ bd,
                         const float* __restrict__ Wa, const float* __restrict__ ba,
                         const float* __restrict__ We, const float* __restrict__ be,
                         const float* __restrict__ base_d, const float* __restrict__ base_a,
                         const float* __restrict__ base_e,
                         const float* __restrict__ gd, const float* __restrict__ ga,
                         const float* __restrict__ ge,
                         float* __restrict__ out)
{
    extern __shared__ float x_sh[];
    const int typ = blockIdx.x >> 6;
    const int h0  = (blockIdx.x & 63) * 8;

    const float* feat = g_feat + (size_t)typ * B_ * C_;
    for (int i = threadIdx.x; i < B_ * C_; i += 256) x_sh[i] = feat[i];
    __syncthreads();

    const float* Wm   = (typ == 0) ? Wd : (typ == 1) ? Wa : We;
    const float* bm   = (typ == 0) ? bd : (typ == 1) ? ba : be;
    const float* bsp  = (typ == 0) ? base_d : (typ == 1) ? base_a : base_e;
    const float  g    = (typ == 0) ? *gd : (typ == 1) ? *ga : *ge;
    const float  sg   = 0.3f / (1.0f + expf(-g));
    const size_t ooff = (typ == 0) ? OUT_D : (typ == 1) ? OUT_A : OUT_E;

    const int lane = threadIdx.x & 31;
    const int h    = h0 + (threadIdx.x >> 5);

    const float4* wrow = (const float4*)(Wm + (size_t)h * C_);
    const float4 w0 = wrow[lane * 2];
    const float4 w1 = wrow[lane * 2 + 1];
    const float  bh = bm[h];

    for (int b = 0; b < B_; b++) {
        const float4* xb = (const float4*)(x_sh + b * C_ + lane * 8);
        const float4 x0 = xb[0], x1 = xb[1];
        float p = w0.x * x0.x + w0.y * x0.y + w0.z * x0.z + w0.w * x0.w
                + w1.x * x1.x + w1.y * x1.y + w1.z * x1.z + w1.w * x1.w;
        #pragma unroll
        for (int off = 16; off > 0; off >>= 1)
            p += __shfl_xor_sync(0xffffffffu, p, off);
        if (lane == 0) {
            const float r = p + bh;
            const float v = bsp[(size_t)b * H_ + h] + sg * r;
            out[ooff + (size_t)b * H_ + h] = v > 0.0f ? v : 0.0f;
        }
    }
}

// ============================================================================
extern "C" void kernel_launch(void* const* d_in, const int* in_sizes, int n_in,
                              void* d_out, int out_size)
{
    const float* tx    = (const float*)d_in[0];
    const float* rxsp  = (const float*)d_in[1];
    const float* bsd   = (const float*)d_in[2];
    const float* bsa   = (const float*)d_in[3];
    const float* bse   = (const float*)d_in[4];
    const float* W_tx  = (const float*)d_in[5];
    const float* b_tx  = (const float*)d_in[6];
    const float* W_rx  = (const float*)d_in[7];
    const float* b_rx  = (const float*)d_in[8];
    const float* Wd    = (const float*)d_in[9];
    const float* bd    = (const float*)d_in[10];
    const float* Wa    = (const float*)d_in[11];
    const float* ba    = (const float*)d_in[12];
    const float* We    = (const float*)d_in[13];
    const float* be    = (const float*)d_in[14];
    const float* gd    = (const float*)d_in[15];
    const float* ga    = (const float*)d_in[16];
    const float* ge    = (const float*)d_in[17];
    float* out = (float*)d_out;

    static bool inited = false;
    static cudaStream_t s2 = 0;
    static cudaEvent_t evFork = 0, evJoin = 0;
    if (!inited) {
        cudaFuncSetAttribute(k_mma, cudaFuncAttributeMaxDynamicSharedMemorySize, SM_MMA_TOTAL);
        cudaFuncSetAttribute(k2a_mix, cudaFuncAttributeMaxDynamicSharedMemorySize, 98832);
        cudaFuncSetAttribute(k4b_head, cudaFuncAttributeMaxDynamicSharedMemorySize, 65536);
        if (cudaStreamCreateWithFlags(&s2, cudaStreamNonBlocking) != cudaSuccess) s2 = 0;
        cudaEventCreateWithFlags(&evFork, cudaEventDisableTiming);
        cudaEventCreateWithFlags(&evJoin, cudaEventDisableTiming);
        inited = true;
    }

    // weights prep (both engines depend on it)
    k0w<<<dim3(2, 64), 256>>>(W_tx, W_rx);

    // ---- fork: branch A (IMMA engine) on s2, branch B (scalar) on default
    cudaEventRecord(evFork, 0);
    cudaStreamWaitEvent(s2, evFork, 0);

    k_mma<<<S_MMA * 64, 256, SM_MMA_TOTAL, s2>>>(tx, rxsp);
    k2b_scan<<<S_MMA * 2, 128, 0, s2>>>(b_tx, b_rx, 0);
    cudaEventRecord(evJoin, s2);

    k1_pack<<<(S_TOT - S_MMA) * 32, 256>>>(tx, rxsp);
    k2a_mix<<<dim3(8, 4, S_TOT - S_MMA), 256, 98832>>>(W_tx, W_rx);
    k2b_scan<<<(S_TOT - S_MMA) * 2, 128>>>(b_tx, b_rx, S_MMA);

    cudaStreamWaitEvent(0, evJoin, 0);

    // ---- tail
    k3_expand<<<4096, 256>>>(out);
    k4a_feat<<<B_, 256>>>(out);
    k4b_head<<<3 * 64, 256, 65536>>>(Wd, bd, Wa, ba, We, be, bsd, bsa, bse, gd, ga, ge, out);
}